// round 3
// baseline (speedup 1.0000x reference)
#include <cuda_runtime.h>
#include <cuda_fp16.h>

#define BATCH 128
#define NRR   4096
#define NC    10
#define NO    16
#define NI    8
#define CO    160   // NC*NO

#define STRIPS 64            // r-strips per batch in k_route
#define RPS    (NRR/STRIPS)  // rows per strip = 64

// ---------------- scratch (static device globals; no allocation) ----------------
__device__ alignas(16) __half g_U[(size_t)BATCH * NRR * CO];   // u_hat fp16 [b][r][c*16+o]
__device__ alignas(16) float  g_bij[(size_t)BATCH * NRR * NC]; // routing logits
__device__ alignas(16) float  g_s[BATCH * CO];                 // accumulated s (pre-bias)
__device__ alignas(16) float  g_v[BATCH * CO];                 // squashed v per iter

// ---------------- zero s ----------------
__global__ void k_zero_s() {
    int i = blockIdx.x * blockDim.x + threadIdx.x;
    if (i < BATCH * CO) g_s[i] = 0.f;
}

// ---------------- K1: u_hat producer + fused s0 = 0.1 * sum_r u_hat ----------------
// grid (NRR/16, BATCH/16), block 160.
// thread t: coq = t%40 -> 4 consecutive (c,o) pairs; bq = t/40 -> batch sublane (4 b's).
__global__ __launch_bounds__(160) void k_uhat(const float* __restrict__ x,
                                              const float* __restrict__ W) {
    const int t   = threadIdx.x;
    const int coq = t % 40;
    const int bq  = t / 40;
    const int rB  = blockIdx.x * 16;
    const int bB  = blockIdx.y * 16;

    // stage all x rows for this (16b x 16r) tile up front: 8KB, one barrier
    __shared__ float4 xs[16][16][2];   // [rr][bl][half]
    for (int i = t; i < 16 * 16 * 2; i += 160) {
        int bl = i >> 5, rr = (i >> 1) & 15, h = i & 1;
        xs[rr][bl][h] =
            reinterpret_cast<const float4*>(x)[(((size_t)(bB + bl) * NRR + rB + rr) << 1) + h];
    }
    __syncthreads();

    float sacc[4][4];
#pragma unroll
    for (int a = 0; a < 4; a++)
#pragma unroll
        for (int j = 0; j < 4; j++) sacc[a][j] = 0.f;

    for (int rr = 0; rr < 16; rr++) {
        const int r = rB + rr;
        const float4* Wv = reinterpret_cast<const float4*>(W + (size_t)r * 1280 + coq * 32);
        float4 w0 = Wv[0], w1 = Wv[1], w2 = Wv[2], w3 = Wv[3];
        float4 w4 = Wv[4], w5 = Wv[5], w6 = Wv[6], w7 = Wv[7];

#pragma unroll
        for (int bb = 0; bb < 4; bb++) {
            const int bl = bq + 4 * bb;
            const float4 xa = xs[rr][bl][0];
            const float4 xb = xs[rr][bl][1];
            float u0 = w0.x*xa.x + w0.y*xa.y + w0.z*xa.z + w0.w*xa.w
                     + w1.x*xb.x + w1.y*xb.y + w1.z*xb.z + w1.w*xb.w;
            float u1 = w2.x*xa.x + w2.y*xa.y + w2.z*xa.z + w2.w*xa.w
                     + w3.x*xb.x + w3.y*xb.y + w3.z*xb.z + w3.w*xb.w;
            float u2 = w4.x*xa.x + w4.y*xa.y + w4.z*xa.z + w4.w*xa.w
                     + w5.x*xb.x + w5.y*xb.y + w5.z*xb.z + w5.w*xb.w;
            float u3 = w6.x*xa.x + w6.y*xa.y + w6.z*xa.z + w6.w*xa.w
                     + w7.x*xb.x + w7.y*xb.y + w7.z*xb.z + w7.w*xb.w;
            sacc[bb][0] += u0; sacc[bb][1] += u1;
            sacc[bb][2] += u2; sacc[bb][3] += u3;

            __half2 p0 = __floats2half2_rn(u0, u1);
            __half2 p1 = __floats2half2_rn(u2, u3);
            uint2 st;
            st.x = *reinterpret_cast<unsigned*>(&p0);
            st.y = *reinterpret_cast<unsigned*>(&p1);
            *reinterpret_cast<uint2*>(g_U + ((size_t)(bB + bl) * NRR + r) * CO + coq * 4) = st;
        }
    }

#pragma unroll
    for (int bb = 0; bb < 4; bb++) {
        const int bg = bB + bq + 4 * bb;
#pragma unroll
        for (int j = 0; j < 4; j++)
            atomicAdd(&g_s[bg * CO + coq * 4 + j], 0.1f * sacc[bb][j]);
    }
}

// ---------------- K2: routing pass (agreement + softmax + s accumulation) ----------------
// warp per (b, r-strip of RPS rows). IT=1: b_new = a (write b_ij). IT=2: b_new = b_ij + a.
template <int IT>
__global__ __launch_bounds__(256) void k_route() {
    const int lane  = threadIdx.x & 31;
    const int w     = blockIdx.x * 8 + (threadIdx.x >> 5);
    const int b     = w / STRIPS;        // 0..127
    const int strip = w % STRIPS;        // 0..STRIPS-1
    const int r0    = strip * RPS;
    const int c0    = lane >> 2;         // capsule for group A (0..7)
    const int c1    = 8 + (lane >> 2);   // capsule for group B (lanes < 8)
    const bool act1 = lane < 8;

    const float4* Vv = reinterpret_cast<const float4*>(g_v + b * CO);
    const float4 va = Vv[lane];
    const float4 vb = act1 ? Vv[32 + lane] : make_float4(0.f, 0.f, 0.f, 0.f);

    float sa0 = 0.f, sa1 = 0.f, sa2 = 0.f, sa3 = 0.f;
    float sb0 = 0.f, sb1 = 0.f, sb2 = 0.f, sb3 = 0.f;

    const __half* Ub = g_U + (size_t)b * NRR * CO;
    float* bij       = g_bij + (size_t)b * NRR * NC;

#pragma unroll 4
    for (int rr = 0; rr < RPS; rr++) {
        const int r = r0 + rr;
        const uint2* Urow = reinterpret_cast<const uint2*>(Ub + (size_t)r * CO);
        uint2 ua = Urow[lane];
        uint2 ub = act1 ? Urow[32 + lane] : make_uint2(0u, 0u);

        float2 fa0 = __half22float2(*reinterpret_cast<__half2*>(&ua.x));
        float2 fa1 = __half22float2(*reinterpret_cast<__half2*>(&ua.y));
        float2 fb0 = __half22float2(*reinterpret_cast<__half2*>(&ub.x));
        float2 fb1 = __half22float2(*reinterpret_cast<__half2*>(&ub.y));

        // agreement partial: u_hat . v  (4 elems/lane/group; reduce over 4-lane group)
        float pa = fa0.x*va.x + fa0.y*va.y + fa1.x*va.z + fa1.y*va.w;
        float pb = fb0.x*vb.x + fb0.y*vb.y + fb1.x*vb.z + fb1.y*vb.w;
        pa += __shfl_xor_sync(0xffffffffu, pa, 1);
        pa += __shfl_xor_sync(0xffffffffu, pa, 2);
        pb += __shfl_xor_sync(0xffffffffu, pb, 1);
        pb += __shfl_xor_sync(0xffffffffu, pb, 2);

        float bna, bnb;
        if (IT == 1) {
            bna = pa; bnb = pb;
        } else {
            bna = bij[r * NC + c0] + pa;
            bnb = (act1 ? bij[r * NC + c1] : 0.f) + pb;
        }

        float ea = __expf(bna);
        float eb = act1 ? __expf(bnb) : 0.f;

        // softmax denominator over 10 capsules
        float s07 = ea;
        s07 += __shfl_xor_sync(0xffffffffu, s07, 4);
        s07 += __shfl_xor_sync(0xffffffffu, s07, 8);
        s07 += __shfl_xor_sync(0xffffffffu, s07, 16);
        float s89 = eb + __shfl_xor_sync(0xffffffffu, eb, 4);
        s89 = __shfl_sync(0xffffffffu, s89, 0);
        float rinv = 1.f / (s07 + s89);

        float ca = ea * rinv;
        float cb = eb * rinv;
        sa0 += ca * fa0.x; sa1 += ca * fa0.y; sa2 += ca * fa1.x; sa3 += ca * fa1.y;
        sb0 += cb * fb0.x; sb1 += cb * fb0.y; sb2 += cb * fb1.x; sb3 += cb * fb1.y;

        if (IT == 1) {
            if ((lane & 3) == 0) bij[r * NC + c0] = bna;
            if (act1 && (lane & 3) == 0) bij[r * NC + c1] = bnb;
        }
    }

    float* srow = g_s + b * CO;
    atomicAdd(&srow[4 * lane + 0], sa0);
    atomicAdd(&srow[4 * lane + 1], sa1);
    atomicAdd(&srow[4 * lane + 2], sa2);
    atomicAdd(&srow[4 * lane + 3], sa3);
    if (act1) {
        atomicAdd(&srow[128 + 4 * lane + 0], sb0);
        atomicAdd(&srow[128 + 4 * lane + 1], sb1);
        atomicAdd(&srow[128 + 4 * lane + 2], sb2);
        atomicAdd(&srow[128 + 4 * lane + 3], sb3);
    }
}

// ---------------- K3: v = squash(s + bias); reset s; optional final output ----------------
// grid BATCH, block 160 (5 warps; each 16-lane half = one capsule)
__global__ __launch_bounds__(160) void k_squash(const float* __restrict__ bias,
                                                float* __restrict__ out, int final_it) {
    const int b = blockIdx.x, t = threadIdx.x;
    float sv = g_s[b * CO + t] + bias[t];
    float q = sv * sv;
    q += __shfl_xor_sync(0xffffffffu, q, 1);
    q += __shfl_xor_sync(0xffffffffu, q, 2);
    q += __shfl_xor_sync(0xffffffffu, q, 4);
    q += __shfl_xor_sync(0xffffffffu, q, 8);
    float vj = sv * (q / ((1.f + q) * sqrtf(q)));
    g_v[b * CO + t] = vj;
    if (final_it) out[b * CO + t] = vj;
    g_s[b * CO + t] = 0.f;   // ready for next accumulation pass
}

// ---------------- launcher ----------------
extern "C" void kernel_launch(void* const* d_in, const int* in_sizes, int n_in,
                              void* d_out, int out_size) {
    const float* x = nullptr;
    const float* W = nullptr;
    const float* bias = nullptr;
    for (int i = 0; i < n_in; i++) {
        if (in_sizes[i] == BATCH * NRR * NI)        x    = (const float*)d_in[i];
        else if (in_sizes[i] == NRR * NC * NO * NI) W    = (const float*)d_in[i];
        else if (in_sizes[i] == NC * NO)            bias = (const float*)d_in[i];
    }
    float* out = (float*)d_out;

    k_zero_s<<<(BATCH * CO + 255) / 256, 256>>>();
    k_uhat<<<dim3(NRR / 16, BATCH / 16), 160>>>(x, W);
    k_squash<<<BATCH, 160>>>(bias, out, 0);              // v0 from fused s0
    k_route<1><<<BATCH * STRIPS / 8, 256>>>();           // a0 -> b1 -> softmax -> s1
    k_squash<<<BATCH, 160>>>(bias, out, 0);              // v1
    k_route<2><<<BATCH * STRIPS / 8, 256>>>();           // a1 -> b2 -> softmax -> s2
    k_squash<<<BATCH, 160>>>(bias, out, 1);              // v2 -> d_out
}

// round 4
// speedup vs baseline: 1.0538x; 1.0538x over previous
#include <cuda_runtime.h>
#include <cuda_fp16.h>

#define BATCH 128
#define NRR   4096
#define NC    10
#define NO    16
#define NI    8
#define CO    160   // NC*NO

#define STRIPS 64            // r-strips per batch in k_route
#define RPS    (NRR/STRIPS)  // rows per strip = 64

// ---------------- scratch (static device globals; no allocation) ----------------
__device__ alignas(16) __half g_U[(size_t)BATCH * NRR * CO];   // u_hat fp16 [b][r][c*16+o]
__device__ alignas(16) float  g_bij[(size_t)BATCH * NRR * NC]; // routing logits
__device__ alignas(16) float  g_s[BATCH * CO];                 // accumulated s (pre-bias)
__device__ alignas(16) float  g_v[BATCH * CO];                 // squashed v per iter

// ---------------- zero s ----------------
__global__ void k_zero_s() {
    int i = blockIdx.x * blockDim.x + threadIdx.x;
    if (i < BATCH * CO) g_s[i] = 0.f;
}

// ---------------- K1: u_hat producer + fused s0 = 0.1 * sum_r u_hat ----------------
// grid (NRR/16, BATCH/16), block 160.
// thread t: coq = t%40 -> 4 consecutive (c,o) pairs; bq = t/40 -> batch sublane (4 b's).
__global__ __launch_bounds__(160) void k_uhat(const float* __restrict__ x,
                                              const float* __restrict__ W) {
    const int t   = threadIdx.x;
    const int coq = t % 40;
    const int bq  = t / 40;
    const int rB  = blockIdx.x * 16;
    const int bB  = blockIdx.y * 16;

    // stage all x rows for this (16b x 16r) tile up front: 8KB, one barrier
    __shared__ float4 xs[16][16][2];   // [rr][bl][half]
    for (int i = t; i < 16 * 16 * 2; i += 160) {
        int bl = i >> 5, rr = (i >> 1) & 15, h = i & 1;
        xs[rr][bl][h] =
            reinterpret_cast<const float4*>(x)[(((size_t)(bB + bl) * NRR + rB + rr) << 1) + h];
    }
    __syncthreads();

    float sacc[4][4];
#pragma unroll
    for (int a = 0; a < 4; a++)
#pragma unroll
        for (int j = 0; j < 4; j++) sacc[a][j] = 0.f;

    for (int rr = 0; rr < 16; rr++) {
        const int r = rB + rr;
        const float4* Wv = reinterpret_cast<const float4*>(W + (size_t)r * 1280 + coq * 32);
        float4 w0 = Wv[0], w1 = Wv[1], w2 = Wv[2], w3 = Wv[3];
        float4 w4 = Wv[4], w5 = Wv[5], w6 = Wv[6], w7 = Wv[7];

#pragma unroll
        for (int bb = 0; bb < 4; bb++) {
            const int bl = bq + 4 * bb;
            const float4 xa = xs[rr][bl][0];
            const float4 xb = xs[rr][bl][1];
            float u0 = w0.x*xa.x + w0.y*xa.y + w0.z*xa.z + w0.w*xa.w
                     + w1.x*xb.x + w1.y*xb.y + w1.z*xb.z + w1.w*xb.w;
            float u1 = w2.x*xa.x + w2.y*xa.y + w2.z*xa.z + w2.w*xa.w
                     + w3.x*xb.x + w3.y*xb.y + w3.z*xb.z + w3.w*xb.w;
            float u2 = w4.x*xa.x + w4.y*xa.y + w4.z*xa.z + w4.w*xa.w
                     + w5.x*xb.x + w5.y*xb.y + w5.z*xb.z + w5.w*xb.w;
            float u3 = w6.x*xa.x + w6.y*xa.y + w6.z*xa.z + w6.w*xa.w
                     + w7.x*xb.x + w7.y*xb.y + w7.z*xb.z + w7.w*xb.w;
            sacc[bb][0] += u0; sacc[bb][1] += u1;
            sacc[bb][2] += u2; sacc[bb][3] += u3;

            __half2 p0 = __floats2half2_rn(u0, u1);
            __half2 p1 = __floats2half2_rn(u2, u3);
            uint2 st;
            st.x = *reinterpret_cast<unsigned*>(&p0);
            st.y = *reinterpret_cast<unsigned*>(&p1);
            *reinterpret_cast<uint2*>(g_U + ((size_t)(bB + bl) * NRR + r) * CO + coq * 4) = st;
        }
    }

#pragma unroll
    for (int bb = 0; bb < 4; bb++) {
        const int bg = bB + bq + 4 * bb;
#pragma unroll
        for (int j = 0; j < 4; j++)
            atomicAdd(&g_s[bg * CO + coq * 4 + j], 0.1f * sacc[bb][j]);
    }
}

// ---------------- K2: routing pass (agreement + softmax + s accumulation) ----------------
// warp per (b, r-strip of RPS rows). Lane -> (capsule slot = lane>>1, o-half = lane&1).
// Active lanes: slot < 10 (20 of 32). Each active lane covers 8 o's of one capsule.
// IT=1: b_new = a (write b_ij). IT=2: b_new = b_ij + a.
template <int IT>
__global__ __launch_bounds__(256) void k_route() {
    const int lane = threadIdx.x & 31;
    const int w    = blockIdx.x * 8 + (threadIdx.x >> 5);
    const int b    = w / STRIPS;         // 0..127
    const int strip= w % STRIPS;
    const int r0   = strip * RPS;
    const int slot = lane >> 1;          // capsule 0..15 (active < 10)
    const int oh   = lane & 1;           // o-half: 0 -> o0..7, 1 -> o8..15
    const bool act = slot < NC;

    // v slice for this (capsule, o-half): 8 floats
    float v0=0,v1=0,v2=0,v3=0,v4=0,v5=0,v6=0,v7=0;
    if (act) {
        const float4* Vv = reinterpret_cast<const float4*>(g_v + b * CO + slot * NO + oh * 8);
        float4 a = Vv[0], c = Vv[1];
        v0=a.x; v1=a.y; v2=a.z; v3=a.w; v4=c.x; v5=c.y; v6=c.z; v7=c.w;
    }

    float ac0=0,ac1=0,ac2=0,ac3=0,ac4=0,ac5=0,ac6=0,ac7=0;

    const __half* Ub = g_U + (size_t)b * NRR * CO;
    float* bij       = g_bij + (size_t)b * NRR * NC;

#pragma unroll 4
    for (int rr = 0; rr < RPS; rr++) {
        const int r = r0 + rr;
        uint4 uu = make_uint4(0u, 0u, 0u, 0u);
        if (act)
            uu = *reinterpret_cast<const uint4*>(Ub + (size_t)r * CO + slot * NO + oh * 8);

        float2 f0 = __half22float2(*reinterpret_cast<__half2*>(&uu.x));
        float2 f1 = __half22float2(*reinterpret_cast<__half2*>(&uu.y));
        float2 f2 = __half22float2(*reinterpret_cast<__half2*>(&uu.z));
        float2 f3 = __half22float2(*reinterpret_cast<__half2*>(&uu.w));

        // agreement partial: u . v over this lane's 8 o's, then pair-reduce (1 shfl)
        float p = f0.x*v0 + f0.y*v1 + f1.x*v2 + f1.y*v3
                + f2.x*v4 + f2.y*v5 + f3.x*v6 + f3.y*v7;
        p += __shfl_xor_sync(0xffffffffu, p, 1);

        float bn;
        if (IT == 1) bn = p;
        else         bn = (act ? bij[r * NC + slot] : 0.f) + p;

        float e = act ? __expf(bn) : 0.f;

        // softmax denominator over 16 slots (inactive contribute 0): 4 shfls
        float Z = e;
        Z += __shfl_xor_sync(0xffffffffu, Z, 2);
        Z += __shfl_xor_sync(0xffffffffu, Z, 4);
        Z += __shfl_xor_sync(0xffffffffu, Z, 8);
        Z += __shfl_xor_sync(0xffffffffu, Z, 16);

        float cc = __fdividef(e, Z);

        ac0 += cc * f0.x; ac1 += cc * f0.y; ac2 += cc * f1.x; ac3 += cc * f1.y;
        ac4 += cc * f2.x; ac5 += cc * f2.y; ac6 += cc * f3.x; ac7 += cc * f3.y;

        if (IT == 1) {
            if (act && oh == 0) bij[r * NC + slot] = bn;
        }
    }

    if (act) {
        float* srow = g_s + b * CO + slot * NO + oh * 8;
        atomicAdd(&srow[0], ac0);
        atomicAdd(&srow[1], ac1);
        atomicAdd(&srow[2], ac2);
        atomicAdd(&srow[3], ac3);
        atomicAdd(&srow[4], ac4);
        atomicAdd(&srow[5], ac5);
        atomicAdd(&srow[6], ac6);
        atomicAdd(&srow[7], ac7);
    }
}

// ---------------- K3: v = squash(s + bias); reset s; optional final output ----------------
// grid BATCH, block 160 (5 warps; each 16-lane half = one capsule)
__global__ __launch_bounds__(160) void k_squash(const float* __restrict__ bias,
                                                float* __restrict__ out, int final_it) {
    const int b = blockIdx.x, t = threadIdx.x;
    float sv = g_s[b * CO + t] + bias[t];
    float q = sv * sv;
    q += __shfl_xor_sync(0xffffffffu, q, 1);
    q += __shfl_xor_sync(0xffffffffu, q, 2);
    q += __shfl_xor_sync(0xffffffffu, q, 4);
    q += __shfl_xor_sync(0xffffffffu, q, 8);
    float vj = sv * (q / ((1.f + q) * sqrtf(q)));
    g_v[b * CO + t] = vj;
    if (final_it) out[b * CO + t] = vj;
    g_s[b * CO + t] = 0.f;   // ready for next accumulation pass
}

// ---------------- launcher ----------------
extern "C" void kernel_launch(void* const* d_in, const int* in_sizes, int n_in,
                              void* d_out, int out_size) {
    const float* x = nullptr;
    const float* W = nullptr;
    const float* bias = nullptr;
    for (int i = 0; i < n_in; i++) {
        if (in_sizes[i] == BATCH * NRR * NI)        x    = (const float*)d_in[i];
        else if (in_sizes[i] == NRR * NC * NO * NI) W    = (const float*)d_in[i];
        else if (in_sizes[i] == NC * NO)            bias = (const float*)d_in[i];
    }
    float* out = (float*)d_out;

    k_zero_s<<<(BATCH * CO + 255) / 256, 256>>>();
    k_uhat<<<dim3(NRR / 16, BATCH / 16), 160>>>(x, W);
    k_squash<<<BATCH, 160>>>(bias, out, 0);              // v0 from fused s0
    k_route<1><<<BATCH * STRIPS / 8, 256>>>();           // a0 -> b1 -> softmax -> s1
    k_squash<<<BATCH, 160>>>(bias, out, 0);              // v1
    k_route<2><<<BATCH * STRIPS / 8, 256>>>();           // a1 -> b2 -> softmax -> s2
    k_squash<<<BATCH, 160>>>(bias, out, 1);              // v2 -> d_out
}